// round 8
// baseline (speedup 1.0000x reference)
#include <cuda_runtime.h>
#include <cuda_fp16.h>
#include <math_constants.h>

#define NN 50000
#define EE 800000
#define FD 128     // feature width (IN_DIM and H*D)

typedef unsigned long long ull;

// ---------------- scratch (static device globals; no allocation) -------------
__device__ uint2  g_featTh[NN * 32];  // fp16 feat, transposed: [n][d]={h0h1,h2h3}
__device__ float  g_h1[NN * FD];      // layer-1 output (ELU'd), PLAIN [n][h*32+d]
__device__ float4 g_el[NN];           // per-node a_l . Wh  (4 heads)
__device__ float4 g_er[NN];           // per-node a_r . Wh  (4 heads)
__device__ float4 g_w[EE];            // per-edge softmax weights (unnormalized)
__device__ int    g_deg[NN];
__device__ int    g_offs[NN + 1];
__device__ int    g_cur[NN];
__device__ int2   g_esd[EE];          // CSR-by-dst: {src, dst} per slot

#define SM_SHIFT 10.0f   // constant softmax shift (any C gives identical math)

__device__ __forceinline__ float lrelu(float x) { return x >= 0.f ? x : 0.2f * x; }
__device__ __forceinline__ float eluf(float x)  { return x > 0.f ? x : expm1f(x); }

// -------- packed f32x2 helpers (PTX-only path; ptxas never auto-fuses) -------
__device__ __forceinline__ ull pk2(float x, float y) {
    ull r; asm("mov.b64 %0, {%1, %2};" : "=l"(r) : "f"(x), "f"(y)); return r;
}
__device__ __forceinline__ void upk2(float& x, float& y, ull v) {
    asm("mov.b64 {%0, %1}, %2;" : "=f"(x), "=f"(y) : "l"(v));
}
__device__ __forceinline__ ull fma2(ull a, ull b, ull c) {
    ull d; asm("fma.rn.f32x2 %0, %1, %2, %3;" : "=l"(d) : "l"(a), "l"(b), "l"(c));
    return d;
}

// ---------------- CSR build --------------------------------------------------
__global__ void k_init() {
    int i = blockIdx.x * blockDim.x + threadIdx.x;
    if (i < NN) { g_deg[i] = 0; g_cur[i] = 0; }
}

__global__ void k_hist(const int4* __restrict__ dst4) {
    int e = blockIdx.x * blockDim.x + threadIdx.x;     // e indexes groups of 4
    if (e < EE / 4) {
        int4 d = dst4[e];
        atomicAdd(&g_deg[d.x], 1);
        atomicAdd(&g_deg[d.y], 1);
        atomicAdd(&g_deg[d.z], 1);
        atomicAdd(&g_deg[d.w], 1);
    }
}

// single-block exclusive scan of g_deg -> g_offs (N=50000 is tiny)
__global__ void k_scan() {
    __shared__ int sh[1024];
    int t = threadIdx.x;
    const int CH = (NN + 1023) / 1024;   // 49
    int base = t * CH;
    int s = 0;
    for (int i = 0; i < CH; i++) { int idx = base + i; if (idx < NN) s += g_deg[idx]; }
    sh[t] = s;
    __syncthreads();
    for (int off = 1; off < 1024; off <<= 1) {
        int v = (t >= off) ? sh[t - off] : 0;
        __syncthreads();
        sh[t] += v;
        __syncthreads();
    }
    int run = (t == 0) ? 0 : sh[t - 1];
    for (int i = 0; i < CH; i++) {
        int idx = base + i;
        if (idx < NN) { g_offs[idx] = run; run += g_deg[idx]; }
    }
    if (t == 1023) g_offs[NN] = sh[1023];
}

__global__ void k_scatter(const int4* __restrict__ src4,
                          const int4* __restrict__ dst4) {
    int e = blockIdx.x * blockDim.x + threadIdx.x;     // groups of 4 edges
    if (e < EE / 4) {
        int4 s = src4[e];
        int4 d = dst4[e];
        int p0 = atomicAdd(&g_cur[d.x], 1);
        int p1 = atomicAdd(&g_cur[d.y], 1);
        int p2 = atomicAdd(&g_cur[d.z], 1);
        int p3 = atomicAdd(&g_cur[d.w], 1);
        g_esd[g_offs[d.x] + p0] = make_int2(s.x, d.x);
        g_esd[g_offs[d.y] + p1] = make_int2(s.y, d.y);
        g_esd[g_offs[d.z] + p2] = make_int2(s.z, d.z);
        g_esd[g_offs[d.w] + p3] = make_int2(s.w, d.w);
    }
}

// ---------------- GEMM + fused el/er -----------------------------------------
// feat[n][c] = sum_k X[n][k] * W[c][k].  64 rows x 128 cols / block, 256 thr.
// f32x2 micro-tile: thread (tr,tc) owns rows tr*4..+3, column pairs
// p = tc + 16*jp -> cols {2p, 2p+1}; head = jp, d = {2tc, 2tc+1}.
// Epilogue: writes fp16 transposed featTh AND reduces el/er across the 16 tc
// lanes (shfl) -> writes g_el/g_er directly (k_elr eliminated).
template <int USEH1>
__global__ __launch_bounds__(256) void k_gemm(const float* __restrict__ Xext,
                                              const float* __restrict__ W,
                                              const float* __restrict__ al,
                                              const float* __restrict__ ar) {
    __shared__ float xs[64 * 33];
    __shared__ ull   ws2[64 * 33];   // [pair p][kk] -> {W[2p][k], W[2p+1][k]}
    const float* __restrict__ X = USEH1 ? g_h1 : Xext;
    int row0 = blockIdx.x * 64;
    int tid = threadIdx.x;
    int tr = tid >> 4;   // 0..15 (row group)
    int tc = tid & 15;   // 0..15 (column-pair group)

    // per-thread al/ar slice: float2 {a[h*32+2tc], a[h*32+2tc+1]} per head
    float2 alv[4], arv[4];
#pragma unroll
    for (int h = 0; h < 4; h++) {
        alv[h] = ((const float2*)al)[h * 16 + tc];
        arv[h] = ((const float2*)ar)[h * 16 + tc];
    }

    ull acc[4][4];
#pragma unroll
    for (int i = 0; i < 4; i++)
#pragma unroll
        for (int j = 0; j < 4; j++) acc[i][j] = 0ull;

    float* ws2f = (float*)ws2;
    for (int k0 = 0; k0 < FD; k0 += 32) {
        for (int i = tid; i < 128 * 32; i += 256) {
            int c = i >> 5, kk = i & 31;
            ws2f[(c >> 1) * 66 + kk * 2 + (c & 1)] = W[c * FD + k0 + kk];
        }
        for (int i = tid; i < 64 * 32; i += 256) {
            int r = i >> 5, kk = i & 31;
            int gr = row0 + r;
            xs[r * 33 + kk] = (gr < NN) ? X[(size_t)gr * FD + k0 + kk] : 0.f;
        }
        __syncthreads();
#pragma unroll 4
        for (int kk = 0; kk < 32; kk++) {
            ull aP[4];
#pragma unroll
            for (int i = 0; i < 4; i++) {
                float a = xs[(tr * 4 + i) * 33 + kk];
                aP[i] = pk2(a, a);
            }
            ull b[4];
#pragma unroll
            for (int jp = 0; jp < 4; jp++) b[jp] = ws2[(tc + 16 * jp) * 33 + kk];
#pragma unroll
            for (int i = 0; i < 4; i++)
#pragma unroll
                for (int jp = 0; jp < 4; jp++)
                    acc[i][jp] = fma2(aP[i], b[jp], acc[i][jp]);
        }
        __syncthreads();
    }

#pragma unroll
    for (int i = 0; i < 4; i++) {
        int r = row0 + tr * 4 + i;
        float xh[4], yh[4];
#pragma unroll
        for (int h = 0; h < 4; h++) upk2(xh[h], yh[h], acc[i][h]);

        // fp16 transposed store (only if in range)
        if (r < NN) {
            uint2 l16, h16;
            half2 t0 = __floats2half2_rn(xh[0], xh[1]);
            half2 t1 = __floats2half2_rn(xh[2], xh[3]);
            half2 t2 = __floats2half2_rn(yh[0], yh[1]);
            half2 t3 = __floats2half2_rn(yh[2], yh[3]);
            l16.x = *(unsigned*)&t0; l16.y = *(unsigned*)&t1;
            h16.x = *(unsigned*)&t2; h16.y = *(unsigned*)&t3;
            g_featTh[(size_t)r * 32 + 2 * tc]     = l16;
            g_featTh[(size_t)r * 32 + 2 * tc + 1] = h16;
        }

        // fused el/er: partial per thread, reduce across 16 tc lanes
        float elp[4], erp[4];
#pragma unroll
        for (int h = 0; h < 4; h++) {
            elp[h] = fmaf(xh[h], alv[h].x, yh[h] * alv[h].y);
            erp[h] = fmaf(xh[h], arv[h].x, yh[h] * arv[h].y);
        }
#pragma unroll
        for (int off = 8; off > 0; off >>= 1) {
#pragma unroll
            for (int h = 0; h < 4; h++) {
                elp[h] += __shfl_xor_sync(0xFFFFFFFFu, elp[h], off);
                erp[h] += __shfl_xor_sync(0xFFFFFFFFu, erp[h], off);
            }
        }
        if (tc == 0 && r < NN) {
            g_el[r] = make_float4(elp[0], elp[1], elp[2], elp[3]);
            g_er[r] = make_float4(erp[0], erp[1], erp[2], erp[3]);
        }
    }
}

// ---------------- edge-parallel softmax weights ------------------------------
__global__ __launch_bounds__(256) void k_w() {
    int e = blockIdx.x * blockDim.x + threadIdx.x;
    if (e >= EE) return;
    int2 sd = g_esd[e];
    float4 el4 = g_el[sd.x];
    float4 er4 = g_er[sd.y];
    float4 w4;
    w4.x = __expf(lrelu(el4.x + er4.x) - SM_SHIFT);
    w4.y = __expf(lrelu(el4.y + er4.y) - SM_SHIFT);
    w4.z = __expf(lrelu(el4.z + er4.z) - SM_SHIFT);
    w4.w = __expf(lrelu(el4.w + er4.w) - SM_SHIFT);
    g_w[e] = w4;
}

// ---------------- per-dst-node aggregation (one warp/node) -------------------
// Chunk stage: two coalesced loads (esd.x, w) per lane.
// Broadcast stage: per edge one LDS.128 + one fp16 LDG.64 (all 4 heads) + FMAs.
template <bool LAST>
__global__ __launch_bounds__(256) void k_agg(float* __restrict__ out) {
    __shared__ float4 sw[8][32];   // per-warp staged edge weights
    __shared__ int    si[8][32];   // per-warp staged src indices

    int warp = (blockIdx.x * blockDim.x + threadIdx.x) >> 5;
    int lane = threadIdx.x & 31;
    int w8   = (threadIdx.x >> 5) & 7;
    if (warp >= NN) return;
    int n = warp;
    int beg = g_offs[n], end = g_offs[n + 1];

    if (beg == end) {   // no incoming edges: segment sums are 0 -> elu(0)=0
        if (LAST) out[(size_t)n * 32 + lane] = 0.f;
        else {
#pragma unroll
            for (int k = 0; k < 4; k++) g_h1[(size_t)n * FD + k * 32 + lane] = 0.f;
        }
        return;
    }

    float a0 = 0.f, a1 = 0.f, a2 = 0.f, a3 = 0.f;
    float s0 = 0.f, s1 = 0.f, s2 = 0.f, s3 = 0.f;
    for (int chunk = beg; chunk < end; chunk += 32) {
        int cnt = min(32, end - chunk);
        int j = chunk + lane;
        float4 w4 = make_float4(0.f, 0.f, 0.f, 0.f);
        int s = 0;
        if (j < end) {
            s  = g_esd[j].x;   // coalesced (stride-8 int2, .x only)
            w4 = g_w[j];       // coalesced LDG.128
        }
        s0 += w4.x; s1 += w4.y; s2 += w4.z; s3 += w4.w;
        sw[w8][lane] = w4;
        si[w8][lane] = s;
        __syncwarp();
#pragma unroll 8
        for (int t = 0; t < cnt; t++) {
            int ss = si[w8][t];
            float4 w = sw[w8][t];
            uint2 v = g_featTh[(size_t)ss * 32 + lane];   // fp16: 4 heads, 8B
            float2 p0 = __half22float2(*(half2*)&v.x);
            float2 p1 = __half22float2(*(half2*)&v.y);
            a0 = fmaf(w.x, p0.x, a0);
            a1 = fmaf(w.y, p0.y, a1);
            a2 = fmaf(w.z, p1.x, a2);
            a3 = fmaf(w.w, p1.y, a3);
        }
        __syncwarp();
    }
    // reduce per-lane partial denominators across the warp
#pragma unroll
    for (int off = 16; off > 0; off >>= 1) {
        s0 += __shfl_xor_sync(0xFFFFFFFFu, s0, off);
        s1 += __shfl_xor_sync(0xFFFFFFFFu, s1, off);
        s2 += __shfl_xor_sync(0xFFFFFFFFu, s2, off);
        s3 += __shfl_xor_sync(0xFFFFFFFFu, s3, off);
    }

    if (LAST) {
        float r = eluf(a0 / s0) + eluf(a1 / s1) + eluf(a2 / s2) + eluf(a3 / s3);
        out[(size_t)n * 32 + lane] = 0.25f * r;
    } else {
        float* hr = g_h1 + (size_t)n * FD;     // plain layout for layer-2 GEMM
        hr[lane]      = eluf(a0 / s0);
        hr[32 + lane] = eluf(a1 / s1);
        hr[64 + lane] = eluf(a2 / s2);
        hr[96 + lane] = eluf(a3 / s3);
    }
}

// ---------------- launch -----------------------------------------------------
extern "C" void kernel_launch(void* const* d_in, const int* in_sizes, int n_in,
                              void* d_out, int out_size) {
    const float* x   = (const float*)d_in[0];
    const int*   src = (const int*)d_in[1];   // JAX default: int32 (no x64)
    const int*   dst = (const int*)d_in[2];
    const float* W1  = (const float*)d_in[3];
    const float* al1 = (const float*)d_in[4];
    const float* ar1 = (const float*)d_in[5];
    const float* W2  = (const float*)d_in[6];
    const float* al2 = (const float*)d_in[7];
    const float* ar2 = (const float*)d_in[8];
    float* out = (float*)d_out;

    // CSR build (structure identical for both layers)
    k_init   <<<(NN + 255) / 256, 256>>>();
    k_hist   <<<(EE / 4 + 255) / 256, 256>>>((const int4*)dst);
    k_scan   <<<1, 1024>>>();
    k_scatter<<<(EE / 4 + 255) / 256, 256>>>((const int4*)src, (const int4*)dst);

    int gemmB = (NN + 63) / 64;          // 64 rows per block
    int warpB = (NN + 7) / 8;            // 8 warps per block, 1 warp per node
    int edgeB = (EE + 255) / 256;

    // layer 1
    k_gemm<0><<<gemmB, 256>>>(x, W1, al1, ar1);
    k_w     <<<edgeB, 256>>>();
    k_agg<false><<<warpB, 256>>>(out);   // out unused when !LAST

    // layer 2 (+ fused ELU + head-mean epilogue)
    k_gemm<1><<<gemmB, 256>>>(x, W2, al2, ar2);   // x unused when USEH1
    k_w     <<<edgeB, 256>>>();
    k_agg<true><<<warpB, 256>>>(out);
}